// round 1
// baseline (speedup 1.0000x reference)
#include <cuda_runtime.h>
#include <cuda_bf16.h>
#include <math.h>

// Problem constants
#define B_   2
#define T_   2048
#define C_   512
#define H_   8
#define D_   64
#define BH_  (B_*H_)          // 16
#define L_   128              // chunk length
#define NC_  (T_/L_)          // 16 chunks
#define M_   (B_*T_)          // 4096 rows
#define EPS_ 1e-8f

// Scratch (device globals; no runtime allocation allowed)
__device__ float g_phiq[BH_*T_*D_];   // 8 MB
__device__ float g_phik[BH_*T_*D_];   // 8 MB
__device__ float g_v   [BH_*T_*D_];   // 8 MB
__device__ float g_kv  [BH_*NC_*D_*D_]; // 4 MB  (chunk KV sums -> exclusive prefixes)
__device__ float g_ks  [BH_*NC_*D_];    // 64 KB (chunk K sums -> exclusive prefixes)
__device__ float g_y   [M_*C_];       // 8 MB

__device__ __forceinline__ float phi_fn(float x) {
    return (x > 0.f) ? (x + 1.f) : __expf(x);
}

// ---------------------------------------------------------------------------
// Kernel 1: QKV GEMM  (M=4096, N=1536, K=512) fused with phi + mask + scatter
// Tiles: BM=128, BN=64, BK=16; 256 threads; per-thread 8x4 outputs.
// ---------------------------------------------------------------------------
__global__ void __launch_bounds__(256, 2)
qkv_gemm_kernel(const float* __restrict__ X,
                const float* __restrict__ W,
                const float* __restrict__ bias,
                const float* __restrict__ am)
{
    __shared__ float As[16][128];
    __shared__ float Bs[16][64];

    const int tid = threadIdx.x;
    const int bm = blockIdx.x * 128;
    const int bn = blockIdx.y * 64;
    const int tr = tid >> 4, tc = tid & 15;
    const int m0 = tr * 8, n0 = tc * 4;

    float acc[8][4];
#pragma unroll
    for (int i = 0; i < 8; i++)
#pragma unroll
        for (int j = 0; j < 4; j++) acc[i][j] = 0.f;

    for (int k0 = 0; k0 < 512; k0 += 16) {
        // Load A tile 128x16 (512 float4, 2 per thread), transpose into As[k][m]
#pragma unroll
        for (int q = 0; q < 2; q++) {
            int f = q * 256 + tid;
            int row = f >> 2, kk4 = f & 3;
            float4 a = *(const float4*)&X[(size_t)(bm + row) * 512 + k0 + kk4 * 4];
            As[kk4 * 4 + 0][row] = a.x;
            As[kk4 * 4 + 1][row] = a.y;
            As[kk4 * 4 + 2][row] = a.z;
            As[kk4 * 4 + 3][row] = a.w;
        }
        // Load B tile 16x64
        {
            int kr = tid >> 4, n4 = tid & 15;
            *(float4*)&Bs[kr][n4 * 4] =
                *(const float4*)&W[(size_t)(k0 + kr) * 1536 + bn + n4 * 4];
        }
        __syncthreads();
#pragma unroll
        for (int kk = 0; kk < 16; kk++) {
            float4 a0 = *(const float4*)&As[kk][m0];
            float4 a1 = *(const float4*)&As[kk][m0 + 4];
            float4 b0 = *(const float4*)&Bs[kk][n0];
            float a[8] = {a0.x, a0.y, a0.z, a0.w, a1.x, a1.y, a1.z, a1.w};
            float b[4] = {b0.x, b0.y, b0.z, b0.w};
#pragma unroll
            for (int i = 0; i < 8; i++)
#pragma unroll
                for (int j = 0; j < 4; j++) acc[i][j] += a[i] * b[j];
        }
        __syncthreads();
    }

    // Epilogue: bias + phi + diag-mask + scatter to [B,H,T,D]
#pragma unroll
    for (int i = 0; i < 8; i++) {
        int r = bm + m0 + i;
        int b = r >> 11, t = r & 2047;
        float maskd = am[((size_t)b * 2048 + t) * 2048 + t];
#pragma unroll
        for (int j = 0; j < 4; j++) {
            int n = bn + n0 + j;
            float val = acc[i][j] + bias[n];
            int sec = n >> 9;
            int cc = n & 511;
            int h = cc >> 6, d = cc & 63;
            size_t idx = ((size_t)(b * 8 + h) * 2048 + t) * 64 + d;
            if (sec == 0)      g_phiq[idx] = phi_fn(val);
            else if (sec == 1) g_phik[idx] = phi_fn(val) * maskd;
            else               g_v[idx]    = val * maskd;
        }
    }
}

// ---------------------------------------------------------------------------
// Kernel 2: per-chunk KV outer-product sums (64x64) + K sums (64)
// grid = BH*NC = 256 blocks, 256 threads
// ---------------------------------------------------------------------------
__global__ void __launch_bounds__(256, 4)
chunk_kv_kernel()
{
    __shared__ float sk2[32 * 64];
    __shared__ float sv2[32 * 64];

    const int tid = threadIdx.x;
    const int bh = blockIdx.x >> 4;
    const int c  = blockIdx.x & 15;

    const int i  = tid >> 2;          // 0..63
    const int jb = (tid & 3) * 16;    // 0,16,32,48

    float acc[16];
#pragma unroll
    for (int jj = 0; jj < 16; jj++) acc[jj] = 0.f;
    float ks = 0.f;

    const size_t base = ((size_t)bh * T_ + c * L_) * 64;

    for (int tt0 = 0; tt0 < 128; tt0 += 32) {
#pragma unroll
        for (int q = 0; q < 2; q++) {
            int f = q * 256 + tid;
            int row = f >> 4, d4 = f & 15;
            *(float4*)&sk2[row * 64 + d4 * 4] =
                *(const float4*)&g_phik[base + (size_t)(tt0 + row) * 64 + d4 * 4];
            *(float4*)&sv2[row * 64 + d4 * 4] =
                *(const float4*)&g_v[base + (size_t)(tt0 + row) * 64 + d4 * 4];
        }
        __syncthreads();
#pragma unroll 4
        for (int t = 0; t < 32; t++) {
            float kv = sk2[t * 64 + i];
#pragma unroll
            for (int jj = 0; jj < 16; jj++)
                acc[jj] += kv * sv2[t * 64 + jb + jj];
            if (tid < 64) ks += sk2[t * 64 + tid];
        }
        __syncthreads();
    }

    const size_t ob = (size_t)(bh * NC_ + c) * (D_ * D_);
#pragma unroll
    for (int jj = 0; jj < 16; jj++)
        g_kv[ob + (size_t)i * 64 + jb + jj] = acc[jj];
    if (tid < 64)
        g_ks[(size_t)(bh * NC_ + c) * 64 + tid] = ks;
}

// ---------------------------------------------------------------------------
// Kernel 3: exclusive prefix scan over chunks (in place), 16 blocks
// ---------------------------------------------------------------------------
__global__ void __launch_bounds__(256, 4)
chunk_scan_kernel()
{
    const int tid = threadIdx.x;
    const int bh = blockIdx.x;

    float run[16];
#pragma unroll
    for (int q = 0; q < 16; q++) run[q] = 0.f;

    for (int c = 0; c < NC_; c++) {
        size_t base = (size_t)(bh * NC_ + c) * (D_ * D_);
#pragma unroll
        for (int q = 0; q < 16; q++) {
            size_t e = base + q * 256 + tid;
            float tmp = g_kv[e];
            g_kv[e] = run[q];
            run[q] += tmp;
        }
    }
    if (tid < 64) {
        float kr = 0.f;
        for (int c = 0; c < NC_; c++) {
            size_t e = (size_t)(bh * NC_ + c) * 64 + tid;
            float tmp = g_ks[e];
            g_ks[e] = kr;
            kr += tmp;
        }
    }
}

// ---------------------------------------------------------------------------
// Kernel 4: per-chunk attention
//   A = phiq @ phik^T (128x128, causal mask incl diag)
//   num = A@V + phiq@S_prefix ; den = rowsum(A) + phiq . K_prefix
//   y = num / max(den, eps), written back to [B,T,C] layout
// Dynamic SMEM layout (floats):
//   SQ 128x65, SK 128x65, SV 128x65, SA 128x129, SS 64x65, SKP 64, SDEN 128
// ---------------------------------------------------------------------------
#define SQ_OFF   0
#define SK_OFF   8320
#define SV_OFF   16640
#define SA_OFF   24960
#define SS_OFF   41472
#define SKP_OFF  45632
#define SDEN_OFF 45696
#define SMEM4_FLOATS 45824

__global__ void __launch_bounds__(256, 1)
attn_chunk_kernel()
{
    extern __shared__ float sm[];
    const int tid = threadIdx.x;
    const int bh = blockIdx.x >> 4;
    const int c  = blockIdx.x & 15;

    const size_t base = ((size_t)bh * T_ + c * L_) * 64;

    // Load q/k/v chunks (padded stride 65 rows)
    for (int q = 0; q < 32; q++) {
        int f = q * 256 + tid;
        int row = f >> 6, d = f & 63;
        sm[SQ_OFF + row * 65 + d] = g_phiq[base + f];
        sm[SK_OFF + row * 65 + d] = g_phik[base + f];
        sm[SV_OFF + row * 65 + d] = g_v[base + f];
    }
    // Load S prefix (64x64) and K prefix
    {
        size_t sb = (size_t)(bh * NC_ + c) * (D_ * D_);
        for (int q = 0; q < 16; q++) {
            int f = q * 256 + tid;
            int row = f >> 6, d = f & 63;
            sm[SS_OFF + row * 65 + d] = g_kv[sb + f];
        }
        if (tid < 64)
            sm[SKP_OFF + tid] = g_ks[(size_t)(bh * NC_ + c) * 64 + tid];
    }
    __syncthreads();

    const int tr = tid >> 4, tc = tid & 15;

    // Phase A: A = phiq @ phik^T, 8x8 per thread
    {
        const int m0 = tr * 8, s0 = tc * 8;
        float acc[8][8];
#pragma unroll
        for (int i = 0; i < 8; i++)
#pragma unroll
            for (int j = 0; j < 8; j++) acc[i][j] = 0.f;

        for (int d = 0; d < 64; d++) {
            float a[8], b[8];
#pragma unroll
            for (int i = 0; i < 8; i++) a[i] = sm[SQ_OFF + (m0 + i) * 65 + d];
#pragma unroll
            for (int j = 0; j < 8; j++) b[j] = sm[SK_OFF + (s0 + j) * 65 + d];
#pragma unroll
            for (int i = 0; i < 8; i++)
#pragma unroll
                for (int j = 0; j < 8; j++) acc[i][j] += a[i] * b[j];
        }
        // store with causal mask (s <= t)
#pragma unroll
        for (int i = 0; i < 8; i++) {
            int t = m0 + i;
#pragma unroll
            for (int j = 0; j < 8; j++) {
                int s = s0 + j;
                sm[SA_OFF + t * 129 + s] = (s <= t) ? acc[i][j] : 0.f;
            }
        }
    }
    __syncthreads();

    // Denominator
    if (tid < 128) {
        int t = tid;
        float rs = 0.f;
        for (int s = 0; s < 128; s++) rs += sm[SA_OFF + t * 129 + s];
        for (int d = 0; d < 64; d++)
            rs += sm[SQ_OFF + t * 65 + d] * sm[SKP_OFF + d];
        sm[SDEN_OFF + t] = fmaxf(rs, EPS_);
    }
    __syncthreads();

    // Phase B: num = A@V + phiq@S ; write y
    {
        const int m0 = tr * 8, n0 = tc * 4;
        float num[8][4];
#pragma unroll
        for (int i = 0; i < 8; i++)
#pragma unroll
            for (int j = 0; j < 4; j++) num[i][j] = 0.f;

        for (int k = 0; k < 128; k++) {
            float a[8], b[4];
#pragma unroll
            for (int i = 0; i < 8; i++) a[i] = sm[SA_OFF + (m0 + i) * 129 + k];
#pragma unroll
            for (int j = 0; j < 4; j++) b[j] = sm[SV_OFF + k * 65 + n0 + j];
#pragma unroll
            for (int i = 0; i < 8; i++)
#pragma unroll
                for (int j = 0; j < 4; j++) num[i][j] += a[i] * b[j];
        }
        for (int k = 0; k < 64; k++) {
            float a[8], b[4];
#pragma unroll
            for (int i = 0; i < 8; i++) a[i] = sm[SQ_OFF + (m0 + i) * 65 + k];
#pragma unroll
            for (int j = 0; j < 4; j++) b[j] = sm[SS_OFF + k * 65 + n0 + j];
#pragma unroll
            for (int i = 0; i < 8; i++)
#pragma unroll
                for (int j = 0; j < 4; j++) num[i][j] += a[i] * b[j];
        }

        const int bidx = bh >> 3, h = bh & 7;
#pragma unroll
        for (int i = 0; i < 8; i++) {
            int tl = m0 + i;
            int tg = c * L_ + tl;
            float inv = 1.f / sm[SDEN_OFF + tl];
            size_t ybase = ((size_t)bidx * T_ + tg) * C_ + h * 64 + n0;
#pragma unroll
            for (int j = 0; j < 4; j++)
                g_y[ybase + j] = num[i][j] * inv;
        }
    }
}

// ---------------------------------------------------------------------------
// Kernel 5: output projection GEMM (M=4096, N=512, K=512) + bias -> d_out
// ---------------------------------------------------------------------------
__global__ void __launch_bounds__(256, 2)
proj_gemm_kernel(const float* __restrict__ W,
                 const float* __restrict__ bias,
                 float* __restrict__ out)
{
    __shared__ float As[16][128];
    __shared__ float Bs[16][64];

    const int tid = threadIdx.x;
    const int bm = blockIdx.x * 128;
    const int bn = blockIdx.y * 64;
    const int tr = tid >> 4, tc = tid & 15;
    const int m0 = tr * 8, n0 = tc * 4;

    float acc[8][4];
#pragma unroll
    for (int i = 0; i < 8; i++)
#pragma unroll
        for (int j = 0; j < 4; j++) acc[i][j] = 0.f;

    for (int k0 = 0; k0 < 512; k0 += 16) {
#pragma unroll
        for (int q = 0; q < 2; q++) {
            int f = q * 256 + tid;
            int row = f >> 2, kk4 = f & 3;
            float4 a = *(const float4*)&g_y[(size_t)(bm + row) * 512 + k0 + kk4 * 4];
            As[kk4 * 4 + 0][row] = a.x;
            As[kk4 * 4 + 1][row] = a.y;
            As[kk4 * 4 + 2][row] = a.z;
            As[kk4 * 4 + 3][row] = a.w;
        }
        {
            int kr = tid >> 4, n4 = tid & 15;
            *(float4*)&Bs[kr][n4 * 4] =
                *(const float4*)&W[(size_t)(k0 + kr) * 512 + bn + n4 * 4];
        }
        __syncthreads();
#pragma unroll
        for (int kk = 0; kk < 16; kk++) {
            float4 a0 = *(const float4*)&As[kk][m0];
            float4 a1 = *(const float4*)&As[kk][m0 + 4];
            float4 b0 = *(const float4*)&Bs[kk][n0];
            float a[8] = {a0.x, a0.y, a0.z, a0.w, a1.x, a1.y, a1.z, a1.w};
            float b[4] = {b0.x, b0.y, b0.z, b0.w};
#pragma unroll
            for (int i = 0; i < 8; i++)
#pragma unroll
                for (int j = 0; j < 4; j++) acc[i][j] += a[i] * b[j];
        }
        __syncthreads();
    }

#pragma unroll
    for (int i = 0; i < 8; i++) {
        int r = bm + m0 + i;
#pragma unroll
        for (int j = 0; j < 4; j++) {
            int n = bn + n0 + j;
            out[(size_t)r * 512 + n] = acc[i][j] + bias[n];
        }
    }
}

// ---------------------------------------------------------------------------
extern "C" void kernel_launch(void* const* d_in, const int* in_sizes, int n_in,
                              void* d_out, int out_size)
{
    const float* x     = (const float*)d_in[0];
    const float* am    = (const float*)d_in[1];
    const float* wqkv  = (const float*)d_in[2];
    const float* bqkv  = (const float*)d_in[3];
    const float* wproj = (const float*)d_in[4];
    const float* bproj = (const float*)d_in[5];
    float* out = (float*)d_out;

    static bool attr_set = false;
    if (!attr_set) {
        cudaFuncSetAttribute(attn_chunk_kernel,
                             cudaFuncAttributeMaxDynamicSharedMemorySize,
                             SMEM4_FLOATS * sizeof(float));
        attr_set = true;
    }

    dim3 g1(M_ / 128, 1536 / 64);
    qkv_gemm_kernel<<<g1, 256>>>(x, wqkv, bqkv, am);

    chunk_kv_kernel<<<BH_ * NC_, 256>>>();
    chunk_scan_kernel<<<BH_, 256>>>();

    attn_chunk_kernel<<<BH_ * NC_, 256, SMEM4_FLOATS * sizeof(float)>>>();

    dim3 g5(M_ / 128, 512 / 64);
    proj_gemm_kernel<<<g5, 256>>>(wproj, bproj, out);
}

// round 3
// speedup vs baseline: 1.4224x; 1.4224x over previous
#include <cuda_runtime.h>
#include <cuda_bf16.h>
#include <mma.h>
#include <cstdint>
#include <math.h>

using namespace nvcuda;

// Problem constants
#define B_   2
#define T_   2048
#define C_   512
#define H_   8
#define D_   64
#define BH_  (B_*H_)          // 16
#define L_   128              // chunk length
#define NC_  (T_/L_)          // 16 chunks
#define M_   (B_*T_)          // 4096 rows
#define EPS_ 1e-8f

// Scratch (device globals; no runtime allocation allowed)
__device__ float g_phiq[BH_*T_*D_];
__device__ float g_phik[BH_*T_*D_];
__device__ float g_v   [BH_*T_*D_];
__device__ float g_kv  [BH_*NC_*D_*D_];
__device__ float g_ks  [BH_*NC_*D_];
__device__ float g_y   [M_*C_];

__device__ __forceinline__ float phi_fn(float x) {
    return (x > 0.f) ? (x + 1.f) : __expf(x);
}

// ---------------------------------------------------------------------------
// wmma bf16 GEMM with 3-term bf16 split (fp32-accurate).
//   C[128,64] = A[128,512] * W[512, NW] tile  (+bias, fused epilogue)
// MODE 0: QKV (NW=1536): epilogue = bias + phi + mask + scatter to q/k/v
// MODE 1: proj (NW=512): A = g_y, epilogue = bias + store to out
//
// Tiles: BM=128, BN=64, BK=32; 256 threads = 8 warps (4x2), warp tile 32x32.
// SMEM (bytes): AHI@0 (128x40 bf16), ALO@10240, BHI@20480 (32x72 bf16),
//               BLO@25088, C@29696 (128x68 f32). Total 64512.
// ---------------------------------------------------------------------------
#define AHI_OFF 0
#define ALO_OFF 10240
#define BHI_OFF 20480
#define BLO_OFF 25088
#define CS_OFF  29696
#define GEMM_SMEM 64512
#define LDA 40
#define LDB 72
#define LDC 68

template<int MODE>
__global__ void __launch_bounds__(256)
wmma_gemm_kernel(const float* __restrict__ Xin,
                 const float* __restrict__ Wmat,
                 const float* __restrict__ bias,
                 const float* __restrict__ am,
                 float* __restrict__ outp)
{
    constexpr int NW = (MODE == 0) ? 1536 : 512;
    extern __shared__ char smem[];
    __nv_bfloat16* As_hi = (__nv_bfloat16*)(smem + AHI_OFF);
    __nv_bfloat16* As_lo = (__nv_bfloat16*)(smem + ALO_OFF);
    __nv_bfloat16* Bs_hi = (__nv_bfloat16*)(smem + BHI_OFF);
    __nv_bfloat16* Bs_lo = (__nv_bfloat16*)(smem + BLO_OFF);
    float*         Cs    = (float*)(smem + CS_OFF);

    const int tid = threadIdx.x;
    const int wid = tid >> 5;
    const int bm = blockIdx.x * 128, bn = blockIdx.y * 64;
    const int wr = wid >> 1, wc = wid & 1;   // warp row (0-3), col (0-1)

    const float* Asrc = (MODE == 0) ? Xin : (const float*)g_y;

    wmma::fragment<wmma::accumulator, 16, 16, 16, float> acc[2][2];
#pragma unroll
    for (int i = 0; i < 2; i++)
#pragma unroll
        for (int j = 0; j < 2; j++) wmma::fill_fragment(acc[i][j], 0.f);

    for (int k0 = 0; k0 < 512; k0 += 32) {
        // Load + convert A tile: 128 x 32 f32 -> hi/lo bf16
#pragma unroll
        for (int q = 0; q < 4; q++) {
            int f = q * 256 + tid;            // float4 idx 0..1023
            int row = f >> 3, c4 = (f & 7) * 4;
            float4 v = *(const float4*)&Asrc[(size_t)(bm + row) * 512 + k0 + c4];
            float vv[4] = {v.x, v.y, v.z, v.w};
            int base = row * LDA + c4;
#pragma unroll
            for (int u = 0; u < 4; u++) {
                __nv_bfloat16 h = __float2bfloat16(vv[u]);
                As_hi[base + u] = h;
                As_lo[base + u] = __float2bfloat16(vv[u] - __bfloat162float(h));
            }
        }
        // Load + convert B tile: 32 x 64 f32 (row-major k x n)
#pragma unroll
        for (int q = 0; q < 2; q++) {
            int f = q * 256 + tid;            // float4 idx 0..511
            int row = f >> 4, c4 = (f & 15) * 4;
            float4 v = *(const float4*)&Wmat[(size_t)(k0 + row) * NW + bn + c4];
            float vv[4] = {v.x, v.y, v.z, v.w};
            int base = row * LDB + c4;
#pragma unroll
            for (int u = 0; u < 4; u++) {
                __nv_bfloat16 h = __float2bfloat16(vv[u]);
                Bs_hi[base + u] = h;
                Bs_lo[base + u] = __float2bfloat16(vv[u] - __bfloat162float(h));
            }
        }
        __syncthreads();

#pragma unroll
        for (int kk = 0; kk < 32; kk += 16) {
            wmma::fragment<wmma::matrix_a, 16, 16, 16, __nv_bfloat16, wmma::row_major> ah[2], al[2];
            wmma::fragment<wmma::matrix_b, 16, 16, 16, __nv_bfloat16, wmma::row_major> bh[2], bl[2];
#pragma unroll
            for (int i = 0; i < 2; i++) {
                wmma::load_matrix_sync(ah[i], &As_hi[(wr * 32 + i * 16) * LDA + kk], LDA);
                wmma::load_matrix_sync(al[i], &As_lo[(wr * 32 + i * 16) * LDA + kk], LDA);
            }
#pragma unroll
            for (int j = 0; j < 2; j++) {
                wmma::load_matrix_sync(bh[j], &Bs_hi[kk * LDB + wc * 32 + j * 16], LDB);
                wmma::load_matrix_sync(bl[j], &Bs_lo[kk * LDB + wc * 32 + j * 16], LDB);
            }
#pragma unroll
            for (int i = 0; i < 2; i++)
#pragma unroll
                for (int j = 0; j < 2; j++) {
                    wmma::mma_sync(acc[i][j], ah[i], bh[j], acc[i][j]);
                    wmma::mma_sync(acc[i][j], ah[i], bl[j], acc[i][j]);
                    wmma::mma_sync(acc[i][j], al[i], bh[j], acc[i][j]);
                }
        }
        __syncthreads();
    }

    // Stage C to smem
#pragma unroll
    for (int i = 0; i < 2; i++)
#pragma unroll
        for (int j = 0; j < 2; j++)
            wmma::store_matrix_sync(&Cs[(wr * 32 + i * 16) * LDC + wc * 32 + j * 16],
                                    acc[i][j], LDC, wmma::mem_row_major);
    __syncthreads();

    // Epilogue: each thread handles one 32-col half of one row
    {
        const int row = tid >> 1;             // 0..127
        const int c0  = (tid & 1) * 32;       // 0 or 32
        const int m = bm + row;
        const int n0 = bn + c0;

        if (MODE == 0) {
            const int b = m >> 11, t = m & 2047;
            const float maskd = am[((size_t)b * 2048 + t) * 2048 + t];
            const int sec = bn >> 9;
            const int h = (bn & 511) >> 6;
            float* dst = (sec == 0) ? g_phiq : (sec == 1) ? g_phik : g_v;
            const size_t ob = ((size_t)(b * 8 + h) * 2048 + t) * 64 + (n0 & 63);
#pragma unroll
            for (int c4 = 0; c4 < 32; c4 += 4) {
                float4 bi = *(const float4*)&bias[n0 + c4];
                float bb[4] = {bi.x, bi.y, bi.z, bi.w};
                float ov[4];
#pragma unroll
                for (int u = 0; u < 4; u++) {
                    float val = Cs[row * LDC + c0 + c4 + u] + bb[u];
                    if (sec == 0)      ov[u] = phi_fn(val);
                    else if (sec == 1) ov[u] = phi_fn(val) * maskd;
                    else               ov[u] = val * maskd;
                }
                float4 o; o.x = ov[0]; o.y = ov[1]; o.z = ov[2]; o.w = ov[3];
                *(float4*)&dst[ob + c4] = o;
            }
        } else {
#pragma unroll
            for (int c4 = 0; c4 < 32; c4 += 4) {
                float4 bi = *(const float4*)&bias[n0 + c4];
                float4 o;
                o.x = Cs[row * LDC + c0 + c4 + 0] + bi.x;
                o.y = Cs[row * LDC + c0 + c4 + 1] + bi.y;
                o.z = Cs[row * LDC + c0 + c4 + 2] + bi.z;
                o.w = Cs[row * LDC + c0 + c4 + 3] + bi.w;
                *(float4*)&outp[(size_t)m * 512 + n0 + c4] = o;
            }
        }
    }
}

// ---------------------------------------------------------------------------
// Kernel 2: per-chunk KV outer-product sums (64x64) + K sums (64)
// ---------------------------------------------------------------------------
__global__ void __launch_bounds__(256, 4)
chunk_kv_kernel()
{
    __shared__ float sk2[32 * 64];
    __shared__ float sv2[32 * 64];

    const int tid = threadIdx.x;
    const int bh = blockIdx.x >> 4;
    const int c  = blockIdx.x & 15;

    const int i  = tid >> 2;
    const int jb = (tid & 3) * 16;

    float acc[16];
#pragma unroll
    for (int jj = 0; jj < 16; jj++) acc[jj] = 0.f;
    float ks = 0.f;

    const size_t base = ((size_t)bh * T_ + c * L_) * 64;

    for (int tt0 = 0; tt0 < 128; tt0 += 32) {
#pragma unroll
        for (int q = 0; q < 2; q++) {
            int f = q * 256 + tid;
            int row = f >> 4, d4 = f & 15;
            *(float4*)&sk2[row * 64 + d4 * 4] =
                *(const float4*)&g_phik[base + (size_t)(tt0 + row) * 64 + d4 * 4];
            *(float4*)&sv2[row * 64 + d4 * 4] =
                *(const float4*)&g_v[base + (size_t)(tt0 + row) * 64 + d4 * 4];
        }
        __syncthreads();
#pragma unroll 4
        for (int t = 0; t < 32; t++) {
            float kv = sk2[t * 64 + i];
#pragma unroll
            for (int jj = 0; jj < 16; jj++)
                acc[jj] += kv * sv2[t * 64 + jb + jj];
            if (tid < 64) ks += sk2[t * 64 + tid];
        }
        __syncthreads();
    }

    const size_t ob = (size_t)(bh * NC_ + c) * (D_ * D_);
#pragma unroll
    for (int jj = 0; jj < 16; jj++)
        g_kv[ob + (size_t)i * 64 + jb + jj] = acc[jj];
    if (tid < 64)
        g_ks[(size_t)(bh * NC_ + c) * 64 + tid] = ks;
}

// ---------------------------------------------------------------------------
// Kernel 3: exclusive prefix scan over chunks (in place), 16 blocks
// ---------------------------------------------------------------------------
__global__ void __launch_bounds__(256, 4)
chunk_scan_kernel()
{
    const int tid = threadIdx.x;
    const int bh = blockIdx.x;

    float run[16];
#pragma unroll
    for (int q = 0; q < 16; q++) run[q] = 0.f;

    for (int c = 0; c < NC_; c++) {
        size_t base = (size_t)(bh * NC_ + c) * (D_ * D_);
#pragma unroll
        for (int q = 0; q < 16; q++) {
            size_t e = base + q * 256 + tid;
            float tmp = g_kv[e];
            g_kv[e] = run[q];
            run[q] += tmp;
        }
    }
    if (tid < 64) {
        float kr = 0.f;
        for (int c = 0; c < NC_; c++) {
            size_t e = (size_t)(bh * NC_ + c) * 64 + tid;
            float tmp = g_ks[e];
            g_ks[e] = kr;
            kr += tmp;
        }
    }
}

// ---------------------------------------------------------------------------
// Kernel 4: per-chunk attention
// ---------------------------------------------------------------------------
#define SQ_OFF   0
#define SK_OFF   8320
#define SV_OFF   16640
#define SA_OFF   24960
#define SS_OFF   41472
#define SKP_OFF  45632
#define SDEN_OFF 45696
#define SMEM4_FLOATS 45824

__global__ void __launch_bounds__(256, 1)
attn_chunk_kernel()
{
    extern __shared__ float sm[];
    const int tid = threadIdx.x;
    const int bh = blockIdx.x >> 4;
    const int c  = blockIdx.x & 15;

    const size_t base = ((size_t)bh * T_ + c * L_) * 64;

    for (int q = 0; q < 32; q++) {
        int f = q * 256 + tid;
        int row = f >> 6, d = f & 63;
        sm[SQ_OFF + row * 65 + d] = g_phiq[base + f];
        sm[SK_OFF + row * 65 + d] = g_phik[base + f];
        sm[SV_OFF + row * 65 + d] = g_v[base + f];
    }
    {
        size_t sb = (size_t)(bh * NC_ + c) * (D_ * D_);
        for (int q = 0; q < 16; q++) {
            int f = q * 256 + tid;
            int row = f >> 6, d = f & 63;
            sm[SS_OFF + row * 65 + d] = g_kv[sb + f];
        }
        if (tid < 64)
            sm[SKP_OFF + tid] = g_ks[(size_t)(bh * NC_ + c) * 64 + tid];
    }
    __syncthreads();

    const int tr = tid >> 4, tc = tid & 15;

    {
        const int m0 = tr * 8, s0 = tc * 8;
        float acc[8][8];
#pragma unroll
        for (int i = 0; i < 8; i++)
#pragma unroll
            for (int j = 0; j < 8; j++) acc[i][j] = 0.f;

        for (int d = 0; d < 64; d++) {
            float a[8], b[8];
#pragma unroll
            for (int i = 0; i < 8; i++) a[i] = sm[SQ_OFF + (m0 + i) * 65 + d];
#pragma unroll
            for (int j = 0; j < 8; j++) b[j] = sm[SK_OFF + (s0 + j) * 65 + d];
#pragma unroll
            for (int i = 0; i < 8; i++)
#pragma unroll
                for (int j = 0; j < 8; j++) acc[i][j] += a[i] * b[j];
        }
#pragma unroll
        for (int i = 0; i < 8; i++) {
            int t = m0 + i;
#pragma unroll
            for (int j = 0; j < 8; j++) {
                int s = s0 + j;
                sm[SA_OFF + t * 129 + s] = (s <= t) ? acc[i][j] : 0.f;
            }
        }
    }
    __syncthreads();

    if (tid < 128) {
        int t = tid;
        float rs = 0.f;
        for (int s = 0; s < 128; s++) rs += sm[SA_OFF + t * 129 + s];
        for (int d = 0; d < 64; d++)
            rs += sm[SQ_OFF + t * 65 + d] * sm[SKP_OFF + d];
        sm[SDEN_OFF + t] = fmaxf(rs, EPS_);
    }
    __syncthreads();

    {
        const int m0 = tr * 8, n0 = tc * 4;
        float num[8][4];
#pragma unroll
        for (int i = 0; i < 8; i++)
#pragma unroll
            for (int j = 0; j < 4; j++) num[i][j] = 0.f;

        for (int k = 0; k < 128; k++) {
            float a[8], b[4];
#pragma unroll
            for (int i = 0; i < 8; i++) a[i] = sm[SA_OFF + (m0 + i) * 129 + k];
#pragma unroll
            for (int j = 0; j < 4; j++) b[j] = sm[SV_OFF + k * 65 + n0 + j];
#pragma unroll
            for (int i = 0; i < 8; i++)
#pragma unroll
                for (int j = 0; j < 4; j++) num[i][j] += a[i] * b[j];
        }
        for (int k = 0; k < 64; k++) {
            float a[8], b[4];
#pragma unroll
            for (int i = 0; i < 8; i++) a[i] = sm[SQ_OFF + (m0 + i) * 65 + k];
#pragma unroll
            for (int j = 0; j < 4; j++) b[j] = sm[SS_OFF + k * 65 + n0 + j];
#pragma unroll
            for (int i = 0; i < 8; i++)
#pragma unroll
                for (int j = 0; j < 4; j++) num[i][j] += a[i] * b[j];
        }

        const int bidx = bh >> 3, h = bh & 7;
#pragma unroll
        for (int i = 0; i < 8; i++) {
            int tl = m0 + i;
            int tg = c * L_ + tl;
            float inv = 1.f / sm[SDEN_OFF + tl];
            size_t ybase = ((size_t)bidx * T_ + tg) * C_ + h * 64 + n0;
#pragma unroll
            for (int j = 0; j < 4; j++)
                g_y[ybase + j] = num[i][j] * inv;
        }
    }
}

// ---------------------------------------------------------------------------
extern "C" void kernel_launch(void* const* d_in, const int* in_sizes, int n_in,
                              void* d_out, int out_size)
{
    const float* x     = (const float*)d_in[0];
    const float* am    = (const float*)d_in[1];
    const float* wqkv  = (const float*)d_in[2];
    const float* bqkv  = (const float*)d_in[3];
    const float* wproj = (const float*)d_in[4];
    const float* bproj = (const float*)d_in[5];
    float* out = (float*)d_out;

    static bool attr_set = false;
    if (!attr_set) {
        cudaFuncSetAttribute(attn_chunk_kernel,
                             cudaFuncAttributeMaxDynamicSharedMemorySize,
                             SMEM4_FLOATS * sizeof(float));
        cudaFuncSetAttribute(wmma_gemm_kernel<0>,
                             cudaFuncAttributeMaxDynamicSharedMemorySize, GEMM_SMEM);
        cudaFuncSetAttribute(wmma_gemm_kernel<1>,
                             cudaFuncAttributeMaxDynamicSharedMemorySize, GEMM_SMEM);
        attr_set = true;
    }

    dim3 g1(M_ / 128, 1536 / 64);
    wmma_gemm_kernel<0><<<g1, 256, GEMM_SMEM>>>(x, wqkv, bqkv, am, nullptr);

    chunk_kv_kernel<<<BH_ * NC_, 256>>>();
    chunk_scan_kernel<<<BH_, 256>>>();

    attn_chunk_kernel<<<BH_ * NC_, 256, SMEM4_FLOATS * sizeof(float)>>>();

    dim3 g5(M_ / 128, 512 / 64);
    wmma_gemm_kernel<1><<<g5, 256, GEMM_SMEM>>>(nullptr, wproj, bproj, nullptr, out);
}